// round 5
// baseline (speedup 1.0000x reference)
#include <cuda_runtime.h>
#include <cuda_bf16.h>
#include <cuda_fp16.h>
#include <cstdint>

#define NN 50000
#define NE 800000

// ---------------- device scratch (no allocs allowed) ----------------
__device__ __align__(16) float g_hA[NN * 128];
__device__ __align__(16) float g_hB[NN * 128];
__device__ __align__(16) __half g_h16A[NN * 128];
__device__ __align__(16) __half g_h16B[NN * 128];
__device__ __align__(16) __nv_bfloat16 g_whi[5 * 128 * 128];
__device__ __align__(16) __nv_bfloat16 g_wlo[5 * 128 * 128];
__device__ int   g_deg[NN];
__device__ float g_invdeg[NN];
__device__ int   g_rowptr[NN + 1];
__device__ int   g_epos[NE];
__device__ int   g_esrc[NE];

// ---------------- helpers ----------------
__device__ __forceinline__ uint32_t smem_u32(const void* p) {
    uint32_t a;
    asm("{ .reg .u64 t; cvta.to.shared.u64 t, %1; cvt.u32.u64 %0, t; }" : "=r"(a) : "l"(p));
    return a;
}

__device__ __forceinline__ void ldsm4(uint32_t* r, uint32_t addr) {
    asm volatile("ldmatrix.sync.aligned.m8n8.x4.shared.b16 {%0,%1,%2,%3}, [%4];"
                 : "=r"(r[0]), "=r"(r[1]), "=r"(r[2]), "=r"(r[3]) : "r"(addr));
}

__device__ __forceinline__ void mma_bf16(float* c, const uint32_t* a, const uint32_t* b) {
    asm volatile(
        "mma.sync.aligned.m16n8k16.row.col.f32.bf16.bf16.f32 "
        "{%0,%1,%2,%3}, {%4,%5,%6,%7}, {%8,%9}, {%0,%1,%2,%3};"
        : "+f"(c[0]), "+f"(c[1]), "+f"(c[2]), "+f"(c[3])
        : "r"(a[0]), "r"(a[1]), "r"(a[2]), "r"(a[3]), "r"(b[0]), "r"(b[1]));
}

__device__ __forceinline__ void split_bf16(float v, __nv_bfloat16& hi, __nv_bfloat16& lo) {
    hi = __float2bfloat16_rn(v);
    lo = __float2bfloat16_rn(v - __bfloat162float(hi));
}
__device__ __forceinline__ uint32_t pack2(__nv_bfloat16 a, __nv_bfloat16 b) {
    __nv_bfloat162 t = __halves2bfloat162(a, b);
    return *reinterpret_cast<uint32_t*>(&t);
}
__device__ __forceinline__ uint32_t pack2h(__half a, __half b) {
    __half2 t = __halves2half2(a, b);
    return *reinterpret_cast<uint32_t*>(&t);
}

// ---------------- CSR build ----------------
__global__ void zero_deg_kernel() {
    int v = blockIdx.x * blockDim.x + threadIdx.x;
    if (v < NN) g_deg[v] = 0;
}

// histogram + record within-row position of each edge
__global__ void hist_kernel(const int* __restrict__ dst) {
    int i = blockIdx.x * blockDim.x + threadIdx.x;
    if (i * 4 + 3 < NE) {
        int4 d = ((const int4*)dst)[i];
        int4 p;
        p.x = atomicAdd(&g_deg[d.x], 1);
        p.y = atomicAdd(&g_deg[d.y], 1);
        p.z = atomicAdd(&g_deg[d.z], 1);
        p.w = atomicAdd(&g_deg[d.w], 1);
        ((int4*)g_epos)[i] = p;
    } else {
        for (int e = i * 4; e < NE; ++e) g_epos[e] = atomicAdd(&g_deg[dst[e]], 1);
    }
}

__global__ void scan_kernel() {
    __shared__ int partial[1024];
    int t = threadIdx.x;
    const int C = (NN + 1023) / 1024;
    int beg = t * C;
    int end = min(beg + C, NN);
    int s = 0;
    for (int v = beg; v < end; ++v) s += g_deg[v];
    partial[t] = s;
    __syncthreads();
    for (int off = 1; off < 1024; off <<= 1) {
        int val = (t >= off) ? partial[t - off] : 0;
        __syncthreads();
        partial[t] += val;
        __syncthreads();
    }
    int run = (t == 0) ? 0 : partial[t - 1];
    for (int v = beg; v < end; ++v) {
        int d = g_deg[v];
        g_rowptr[v] = run;
        g_invdeg[v] = 1.0f / (float)(d > 0 ? d : 1);
        run += d;
    }
    if (t == 1023) g_rowptr[NN] = run;
}

// atomic-free scatter fill
__global__ void fill_kernel(const int* __restrict__ src, const int* __restrict__ dst) {
    int i = blockIdx.x * blockDim.x + threadIdx.x;
    if (i * 4 + 3 < NE) {
        int4 s = ((const int4*)src)[i];
        int4 d = ((const int4*)dst)[i];
        int4 p = ((const int4*)g_epos)[i];
        g_esrc[g_rowptr[d.x] + p.x] = s.x;
        g_esrc[g_rowptr[d.y] + p.y] = s.y;
        g_esrc[g_rowptr[d.z] + p.z] = s.z;
        g_esrc[g_rowptr[d.w] + p.w] = s.w;
    } else {
        for (int e = i * 4; e < NE; ++e)
            g_esrc[g_rowptr[dst[e]] + g_epos[e]] = src[e];
    }
}

// ---------------- fp32 -> bf16 split convert (weights only) ----------------
__global__ void convert_split_kernel(const float* __restrict__ in,
                                     __nv_bfloat16* __restrict__ ohi,
                                     __nv_bfloat16* __restrict__ olo, int n4) {
    int i = blockIdx.x * blockDim.x + threadIdx.x;
    if (i < n4) {
        float4 v = ((const float4*)in)[i];
        __nv_bfloat16 h0, l0, h1, l1, h2, l2, h3, l3;
        split_bf16(v.x, h0, l0);
        split_bf16(v.y, h1, l1);
        split_bf16(v.z, h2, l2);
        split_bf16(v.w, h3, l3);
        uint2 uh, ul;
        uh.x = pack2(h0, h1); uh.y = pack2(h2, h3);
        ul.x = pack2(l0, l1); ul.y = pack2(l2, l3);
        ((uint2*)ohi)[i] = uh;
        ((uint2*)olo)[i] = ul;
    }
}

// ---------------- final aggregation (64 feats, post-GEMM reorder) ----------------
__global__ void aggregate_last_kernel(const float* __restrict__ z, const __half* __restrict__ z16,
                                      float* __restrict__ out,
                                      const float* __restrict__ eps,
                                      const float* __restrict__ bl) {
    int warp = (blockIdx.x * blockDim.x + threadIdx.x) >> 5;
    if (warp >= NN) return;
    int lane = threadIdx.x & 31;
    int v = warp;
    int beg = g_rowptr[v], end = g_rowptr[v + 1];
    float2 acc = make_float2(0.f, 0.f);
    int e = beg;
    int col = lane * 2;
#define GATH2(u)                                                       \
    {                                                                  \
        __half2 p = *reinterpret_cast<const __half2*>(&(u));           \
        float2 f = __half22float2(p);                                  \
        acc.x += f.x; acc.y += f.y;                                    \
    }
    for (; e + 8 <= end; e += 8) {
        uint32_t a0 = *(const uint32_t*)(z16 + (size_t)g_esrc[e + 0] * 64 + col);
        uint32_t a1 = *(const uint32_t*)(z16 + (size_t)g_esrc[e + 1] * 64 + col);
        uint32_t a2 = *(const uint32_t*)(z16 + (size_t)g_esrc[e + 2] * 64 + col);
        uint32_t a3 = *(const uint32_t*)(z16 + (size_t)g_esrc[e + 3] * 64 + col);
        uint32_t a4 = *(const uint32_t*)(z16 + (size_t)g_esrc[e + 4] * 64 + col);
        uint32_t a5 = *(const uint32_t*)(z16 + (size_t)g_esrc[e + 5] * 64 + col);
        uint32_t a6 = *(const uint32_t*)(z16 + (size_t)g_esrc[e + 6] * 64 + col);
        uint32_t a7 = *(const uint32_t*)(z16 + (size_t)g_esrc[e + 7] * 64 + col);
        GATH2(a0); GATH2(a1); GATH2(a2); GATH2(a3);
        GATH2(a4); GATH2(a5); GATH2(a6); GATH2(a7);
    }
    for (; e + 4 <= end; e += 4) {
        uint32_t a0 = *(const uint32_t*)(z16 + (size_t)g_esrc[e + 0] * 64 + col);
        uint32_t a1 = *(const uint32_t*)(z16 + (size_t)g_esrc[e + 1] * 64 + col);
        uint32_t a2 = *(const uint32_t*)(z16 + (size_t)g_esrc[e + 2] * 64 + col);
        uint32_t a3 = *(const uint32_t*)(z16 + (size_t)g_esrc[e + 3] * 64 + col);
        GATH2(a0); GATH2(a1); GATH2(a2); GATH2(a3);
    }
    for (; e < end; ++e) {
        uint32_t a = *(const uint32_t*)(z16 + (size_t)g_esrc[e] * 64 + col);
        GATH2(a);
    }
#undef GATH2
    float inv = g_invdeg[v];
    float sc = 1.0f + eps[3];
    float2 zv = *(const float2*)(z + (size_t)v * 64 + col);
    float2 o;
    o.x = sc * zv.x + acc.x * inv + bl[col];
    o.y = sc * zv.y + acc.y * inv + bl[col + 1];
    *(float2*)(out + (size_t)v * 64 + col) = o;
}

// ---------------- fused [aggregate +] GEMM via mma.sync (bf16 split, fp32 accum) ----------------
// AGG=false: A-tile = split(A32[gm])          (SLP input / last-layer h)
// AGG=true : A-tile = split((1+eps[li])*A32[gm] + mean_{s in N(gm)} h16[s])
// out[M,N] = act(Atile @ (Bhi+Blo)^T [+ bias]); also writes fp16 copy to out16.
template <int N, bool RELU, bool BIAS, bool AGG>
__global__ void __launch_bounds__(256) fused_gemm(
    const float* __restrict__ A32, const __half* __restrict__ h16,
    const __nv_bfloat16* __restrict__ Bhi, const __nv_bfloat16* __restrict__ Blo,
    const float* __restrict__ bias, const float* __restrict__ eps, int li,
    float* __restrict__ out, __half* __restrict__ out16, int M) {
    constexpr int LD = 136;
    constexpr int NWN = N / 32;
    constexpr int NWM = 8 / NWN;
    constexpr int MW = 128 / NWM;
    constexpr int MT = MW / 16;

    extern __shared__ __nv_bfloat16 sm[];
    __nv_bfloat16* sAhi = sm;
    __nv_bfloat16* sAlo = sAhi + 128 * LD;
    __nv_bfloat16* sBhi = sAlo + 128 * LD;
    __nv_bfloat16* sBlo = sBhi + N * LD;
    __shared__ float s_bias[128];

    int tid = threadIdx.x;
    int lane = tid & 31;
    int wid = tid >> 5;
    int m0 = blockIdx.x * 128;
    if (BIAS) {
        if (tid < N) s_bias[tid] = bias[tid];
    }

    // ---- B stage first (independent loads issue early) ----
    for (int i = tid; i < N * 16; i += 256) {
        int row = i >> 4;
        int c8 = (i & 15) << 3;
        *(uint4*)&sBhi[row * LD + c8] = *(const uint4*)(Bhi + (size_t)row * 128 + c8);
        *(uint4*)&sBlo[row * LD + c8] = *(const uint4*)(Blo + (size_t)row * 128 + c8);
    }

    // ---- A stage ----
    if (AGG) {
        float sc = 1.0f + eps[li];
        int col = lane * 4;
#define GATH(uv)                                                        \
        {                                                               \
            __half2 p0 = *reinterpret_cast<const __half2*>(&(uv).x);    \
            __half2 p1 = *reinterpret_cast<const __half2*>(&(uv).y);    \
            float2 f0 = __half22float2(p0);                             \
            float2 f1 = __half22float2(p1);                             \
            acc.x += f0.x; acc.y += f0.y; acc.z += f1.x; acc.w += f1.y; \
        }
        for (int j = 0; j < 16; ++j) {
            int row = (wid << 4) + j;
            int gm = m0 + row;
            float4 o = make_float4(0.f, 0.f, 0.f, 0.f);
            if (gm < M) {
                int beg = g_rowptr[gm], end = g_rowptr[gm + 1];
                float4 acc = make_float4(0.f, 0.f, 0.f, 0.f);
                int e = beg;
                for (; e + 8 <= end; e += 8) {
                    uint2 a0 = *(const uint2*)(h16 + (size_t)g_esrc[e + 0] * 128 + col);
                    uint2 a1 = *(const uint2*)(h16 + (size_t)g_esrc[e + 1] * 128 + col);
                    uint2 a2 = *(const uint2*)(h16 + (size_t)g_esrc[e + 2] * 128 + col);
                    uint2 a3 = *(const uint2*)(h16 + (size_t)g_esrc[e + 3] * 128 + col);
                    uint2 a4 = *(const uint2*)(h16 + (size_t)g_esrc[e + 4] * 128 + col);
                    uint2 a5 = *(const uint2*)(h16 + (size_t)g_esrc[e + 5] * 128 + col);
                    uint2 a6 = *(const uint2*)(h16 + (size_t)g_esrc[e + 6] * 128 + col);
                    uint2 a7 = *(const uint2*)(h16 + (size_t)g_esrc[e + 7] * 128 + col);
                    GATH(a0); GATH(a1); GATH(a2); GATH(a3);
                    GATH(a4); GATH(a5); GATH(a6); GATH(a7);
                }
                for (; e + 4 <= end; e += 4) {
                    uint2 a0 = *(const uint2*)(h16 + (size_t)g_esrc[e + 0] * 128 + col);
                    uint2 a1 = *(const uint2*)(h16 + (size_t)g_esrc[e + 1] * 128 + col);
                    uint2 a2 = *(const uint2*)(h16 + (size_t)g_esrc[e + 2] * 128 + col);
                    uint2 a3 = *(const uint2*)(h16 + (size_t)g_esrc[e + 3] * 128 + col);
                    GATH(a0); GATH(a1); GATH(a2); GATH(a3);
                }
                for (; e < end; ++e) {
                    uint2 a = *(const uint2*)(h16 + (size_t)g_esrc[e] * 128 + col);
                    GATH(a);
                }
                float inv = g_invdeg[gm];
                float4 hv = *(const float4*)(A32 + (size_t)gm * 128 + col);
                o.x = sc * hv.x + acc.x * inv;
                o.y = sc * hv.y + acc.y * inv;
                o.z = sc * hv.z + acc.z * inv;
                o.w = sc * hv.w + acc.w * inv;
            }
            __nv_bfloat16 h0, l0, h1, l1, h2, l2, h3, l3;
            split_bf16(o.x, h0, l0);
            split_bf16(o.y, h1, l1);
            split_bf16(o.z, h2, l2);
            split_bf16(o.w, h3, l3);
            uint2 uh, ul;
            uh.x = pack2(h0, h1); uh.y = pack2(h2, h3);
            ul.x = pack2(l0, l1); ul.y = pack2(l2, l3);
            *(uint2*)&sAhi[row * LD + col] = uh;
            *(uint2*)&sAlo[row * LD + col] = ul;
        }
#undef GATH
    } else {
        for (int i = tid; i < 2048; i += 256) {
            int row = i >> 4;
            int c8 = (i & 15) << 3;
            int gm = m0 + row;
            float4 v0 = make_float4(0.f, 0.f, 0.f, 0.f);
            float4 v1 = make_float4(0.f, 0.f, 0.f, 0.f);
            if (gm < M) {
                v0 = *(const float4*)(A32 + (size_t)gm * 128 + c8);
                v1 = *(const float4*)(A32 + (size_t)gm * 128 + c8 + 4);
            }
            __nv_bfloat16 hh[8], ll[8];
            split_bf16(v0.x, hh[0], ll[0]); split_bf16(v0.y, hh[1], ll[1]);
            split_bf16(v0.z, hh[2], ll[2]); split_bf16(v0.w, hh[3], ll[3]);
            split_bf16(v1.x, hh[4], ll[4]); split_bf16(v1.y, hh[5], ll[5]);
            split_bf16(v1.z, hh[6], ll[6]); split_bf16(v1.w, hh[7], ll[7]);
            uint4 uh, ul;
            uh.x = pack2(hh[0], hh[1]); uh.y = pack2(hh[2], hh[3]);
            uh.z = pack2(hh[4], hh[5]); uh.w = pack2(hh[6], hh[7]);
            ul.x = pack2(ll[0], ll[1]); ul.y = pack2(ll[2], ll[3]);
            ul.z = pack2(ll[4], ll[5]); ul.w = pack2(ll[6], ll[7]);
            *(uint4*)&sAhi[row * LD + c8] = uh;
            *(uint4*)&sAlo[row * LD + c8] = ul;
        }
    }
    __syncthreads();

    // ---- MMA mainloop ----
    int wm = wid / NWN;
    int wn = wid % NWN;

    float acc[MT][4][4];
#pragma unroll
    for (int mt = 0; mt < MT; ++mt)
#pragma unroll
        for (int nt = 0; nt < 4; ++nt)
#pragma unroll
            for (int q = 0; q < 4; ++q) acc[mt][nt][q] = 0.f;

    const int ar = lane & 15;
    const int ak = (lane >> 4) << 3;
    const int br = (lane & 7) + ((lane >> 4) << 3);
    const int bk = ((lane >> 3) & 1) << 3;

#pragma unroll
    for (int ks = 0; ks < 8; ++ks) {
        int k0 = ks << 4;
        uint32_t ah[MT][4], al[MT][4];
#pragma unroll
        for (int mt = 0; mt < MT; ++mt) {
            int row = wm * MW + mt * 16 + ar;
            ldsm4(ah[mt], smem_u32(&sAhi[row * LD + k0 + ak]));
            ldsm4(al[mt], smem_u32(&sAlo[row * LD + k0 + ak]));
        }
        uint32_t bh[4][2], bl[4][2];
#pragma unroll
        for (int p = 0; p < 2; ++p) {
            int nrow = wn * 32 + p * 16 + br;
            uint32_t r[4];
            ldsm4(r, smem_u32(&sBhi[nrow * LD + k0 + bk]));
            bh[2 * p][0] = r[0]; bh[2 * p][1] = r[1];
            bh[2 * p + 1][0] = r[2]; bh[2 * p + 1][1] = r[3];
            ldsm4(r, smem_u32(&sBlo[nrow * LD + k0 + bk]));
            bl[2 * p][0] = r[0]; bl[2 * p][1] = r[1];
            bl[2 * p + 1][0] = r[2]; bl[2 * p + 1][1] = r[3];
        }
#pragma unroll
        for (int mt = 0; mt < MT; ++mt)
#pragma unroll
            for (int nt = 0; nt < 4; ++nt) {
                mma_bf16(acc[mt][nt], ah[mt], bh[nt]);
                mma_bf16(acc[mt][nt], ah[mt], bl[nt]);
                mma_bf16(acc[mt][nt], al[mt], bh[nt]);
            }
    }

    // ---- epilogue: fp32 + fp16 dual write ----
    int r = lane >> 2;
    int c2 = (lane & 3) << 1;
#pragma unroll
    for (int mt = 0; mt < MT; ++mt) {
        int gm = m0 + wm * MW + mt * 16 + r;
#pragma unroll
        for (int nt = 0; nt < 4; ++nt) {
            int col = wn * 32 + nt * 8 + c2;
            float b0 = BIAS ? s_bias[col] : 0.f;
            float b1 = BIAS ? s_bias[col + 1] : 0.f;
            if (gm < M) {
                float2 v = make_float2(acc[mt][nt][0] + b0, acc[mt][nt][1] + b1);
                if (RELU) { v.x = fmaxf(v.x, 0.f); v.y = fmaxf(v.y, 0.f); }
                *(float2*)(out + (size_t)gm * N + col) = v;
                *(uint32_t*)(out16 + (size_t)gm * N + col) =
                    pack2h(__float2half_rn(v.x), __float2half_rn(v.y));
            }
            if (gm + 8 < M) {
                float2 v = make_float2(acc[mt][nt][2] + b0, acc[mt][nt][3] + b1);
                if (RELU) { v.x = fmaxf(v.x, 0.f); v.y = fmaxf(v.y, 0.f); }
                *(float2*)(out + (size_t)(gm + 8) * N + col) = v;
                *(uint32_t*)(out16 + (size_t)(gm + 8) * N + col) =
                    pack2h(__float2half_rn(v.x), __float2half_rn(v.y));
            }
        }
    }
}

// ---------------- launch ----------------
extern "C" void kernel_launch(void* const* d_in, const int* in_sizes, int n_in,
                              void* d_out, int out_size) {
    const float* inputs = (const float*)d_in[0];
    const float* fc_W   = (const float*)d_in[1];
    const float* fc_b   = (const float*)d_in[2];
    const float* W      = (const float*)d_in[3];
    const float* b      = (const float*)d_in[4];
    const float* W_last = (const float*)d_in[5];
    const float* b_last = (const float*)d_in[6];
    const float* eps    = (const float*)d_in[7];
    const int*   src    = (const int*)d_in[8];
    const int*   dst    = (const int*)d_in[9];
    float* out = (float*)d_out;

    float *hA, *hB;
    __half *h16A, *h16B;
    __nv_bfloat16 *whi, *wlo;
    cudaGetSymbolAddress((void**)&hA, g_hA);
    cudaGetSymbolAddress((void**)&hB, g_hB);
    cudaGetSymbolAddress((void**)&h16A, g_h16A);
    cudaGetSymbolAddress((void**)&h16B, g_h16B);
    cudaGetSymbolAddress((void**)&whi, g_whi);
    cudaGetSymbolAddress((void**)&wlo, g_wlo);

    const int SMEM128 = (2 * 128 * 136 + 2 * 128 * 136) * 2;  // 139264 B
    const int SMEM64  = (2 * 128 * 136 + 2 * 64 * 136) * 2;   // 104448 B
    cudaFuncSetAttribute(fused_gemm<128, true, true, false>, cudaFuncAttributeMaxDynamicSharedMemorySize, SMEM128);
    cudaFuncSetAttribute(fused_gemm<128, true, true, true>,  cudaFuncAttributeMaxDynamicSharedMemorySize, SMEM128);
    cudaFuncSetAttribute(fused_gemm<64, false, false, false>, cudaFuncAttributeMaxDynamicSharedMemorySize, SMEM64);

    // CSR build (fill is atomic-free via epos)
    zero_deg_kernel<<<(NN + 255) / 256, 256>>>();
    hist_kernel<<<(NE / 4 + 255) / 256, 256>>>(dst);
    scan_kernel<<<1, 1024>>>();
    fill_kernel<<<(NE / 4 + 255) / 256, 256>>>(src, dst);

    // weight bf16 splits
    convert_split_kernel<<<(16384 / 4 + 255) / 256, 256>>>(fc_W, whi, wlo, 16384 / 4);
    convert_split_kernel<<<(49152 / 4 + 255) / 256, 256>>>(W, whi + 16384, wlo + 16384, 49152 / 4);
    convert_split_kernel<<<(8192 / 4 + 255) / 256, 256>>>(W_last, whi + 4 * 16384, wlo + 4 * 16384, 8192 / 4);

    const int gemm_grid = (NN + 127) / 128;  // 391
    const int agg_grid  = (NN + 7) / 8;

    // input SLP: h(A) = relu(inputs @ fcW^T + fcb)
    fused_gemm<128, true, true, false><<<gemm_grid, 256, SMEM128>>>(
        inputs, nullptr, whi, wlo, fc_b, nullptr, 0, hA, h16A, NN);

    // 3 hidden GIN layers, fused aggregate+GEMM, ping-pong A<->B
    fused_gemm<128, true, true, true><<<gemm_grid, 256, SMEM128>>>(
        hA, h16A, whi + 16384, wlo + 16384, b, eps, 0, hB, h16B, NN);
    fused_gemm<128, true, true, true><<<gemm_grid, 256, SMEM128>>>(
        hB, h16B, whi + 2 * 16384, wlo + 2 * 16384, b + 128, eps, 1, hA, h16A, NN);
    fused_gemm<128, true, true, true><<<gemm_grid, 256, SMEM128>>>(
        hA, h16A, whi + 3 * 16384, wlo + 3 * 16384, b + 256, eps, 2, hB, h16B, NN);

    // last layer reordered: z = h @ WL^T (no bias/relu), then out = (1+eps3)z + mean(z16) + bL
    fused_gemm<64, false, false, false><<<gemm_grid, 256, SMEM64>>>(
        hB, nullptr, whi + 4 * 16384, wlo + 4 * 16384, nullptr, nullptr, 0, hA, h16A, NN);
    aggregate_last_kernel<<<agg_grid, 256>>>(hA, h16A, out, eps, b_last);

    (void)in_sizes; (void)n_in; (void)out_size;
}

// round 6
// speedup vs baseline: 1.4738x; 1.4738x over previous
#include <cuda_runtime.h>
#include <cuda_bf16.h>
#include <cstdint>

#define NN 50000
#define NE 800000

// ---------------- device scratch (no allocs allowed) ----------------
__device__ __align__(16) float g_h[NN * 128];
__device__ __align__(16) __nv_bfloat16 g_xhi[NN * 128];
__device__ __align__(16) __nv_bfloat16 g_xlo[NN * 128];
__device__ __align__(16) __nv_bfloat16 g_whi[5 * 128 * 128];
__device__ __align__(16) __nv_bfloat16 g_wlo[5 * 128 * 128];
__device__ int   g_deg[NN];
__device__ float g_invdeg[NN];
__device__ int   g_rowptr[NN + 1];
__device__ int   g_epos[NE];
__device__ int   g_esrc[NE];

// ---------------- helpers ----------------
__device__ __forceinline__ uint32_t smem_u32(const void* p) {
    uint32_t a;
    asm("{ .reg .u64 t; cvta.to.shared.u64 t, %1; cvt.u32.u64 %0, t; }" : "=r"(a) : "l"(p));
    return a;
}

__device__ __forceinline__ void ldsm4(uint32_t* r, uint32_t addr) {
    asm volatile("ldmatrix.sync.aligned.m8n8.x4.shared.b16 {%0,%1,%2,%3}, [%4];"
                 : "=r"(r[0]), "=r"(r[1]), "=r"(r[2]), "=r"(r[3]) : "r"(addr));
}

__device__ __forceinline__ void mma_bf16(float* c, const uint32_t* a, const uint32_t* b) {
    asm volatile(
        "mma.sync.aligned.m16n8k16.row.col.f32.bf16.bf16.f32 "
        "{%0,%1,%2,%3}, {%4,%5,%6,%7}, {%8,%9}, {%0,%1,%2,%3};"
        : "+f"(c[0]), "+f"(c[1]), "+f"(c[2]), "+f"(c[3])
        : "r"(a[0]), "r"(a[1]), "r"(a[2]), "r"(a[3]), "r"(b[0]), "r"(b[1]));
}

__device__ __forceinline__ void split_bf16(float v, __nv_bfloat16& hi, __nv_bfloat16& lo) {
    hi = __float2bfloat16_rn(v);
    lo = __float2bfloat16_rn(v - __bfloat162float(hi));
}
__device__ __forceinline__ uint32_t pack2(__nv_bfloat16 a, __nv_bfloat16 b) {
    __nv_bfloat162 t = __halves2bfloat162(a, b);
    return *reinterpret_cast<uint32_t*>(&t);
}

// ---------------- CSR build ----------------
__global__ void zero_deg_kernel() {
    int v = blockIdx.x * blockDim.x + threadIdx.x;
    if (v < NN) g_deg[v] = 0;
}

// histogram + record within-row position of each edge
__global__ void hist_kernel(const int* __restrict__ dst) {
    int i = blockIdx.x * blockDim.x + threadIdx.x;
    if (i * 4 + 3 < NE) {
        int4 d = ((const int4*)dst)[i];
        int4 p;
        p.x = atomicAdd(&g_deg[d.x], 1);
        p.y = atomicAdd(&g_deg[d.y], 1);
        p.z = atomicAdd(&g_deg[d.z], 1);
        p.w = atomicAdd(&g_deg[d.w], 1);
        ((int4*)g_epos)[i] = p;
    } else {
        for (int e = i * 4; e < NE; ++e) g_epos[e] = atomicAdd(&g_deg[dst[e]], 1);
    }
}

__global__ void scan_kernel() {
    __shared__ int partial[1024];
    int t = threadIdx.x;
    const int C = (NN + 1023) / 1024;
    int beg = t * C;
    int end = min(beg + C, NN);
    int s = 0;
    for (int v = beg; v < end; ++v) s += g_deg[v];
    partial[t] = s;
    __syncthreads();
    for (int off = 1; off < 1024; off <<= 1) {
        int val = (t >= off) ? partial[t - off] : 0;
        __syncthreads();
        partial[t] += val;
        __syncthreads();
    }
    int run = (t == 0) ? 0 : partial[t - 1];
    for (int v = beg; v < end; ++v) {
        int d = g_deg[v];
        g_rowptr[v] = run;
        g_invdeg[v] = 1.0f / (float)(d > 0 ? d : 1);
        run += d;
    }
    if (t == 1023) g_rowptr[NN] = run;
}

// atomic-free scatter fill
__global__ void fill_kernel(const int* __restrict__ src, const int* __restrict__ dst) {
    int i = blockIdx.x * blockDim.x + threadIdx.x;
    if (i * 4 + 3 < NE) {
        int4 s = ((const int4*)src)[i];
        int4 d = ((const int4*)dst)[i];
        int4 p = ((const int4*)g_epos)[i];
        g_esrc[g_rowptr[d.x] + p.x] = s.x;
        g_esrc[g_rowptr[d.y] + p.y] = s.y;
        g_esrc[g_rowptr[d.z] + p.z] = s.z;
        g_esrc[g_rowptr[d.w] + p.w] = s.w;
    } else {
        for (int e = i * 4; e < NE; ++e)
            g_esrc[g_rowptr[dst[e]] + g_epos[e]] = src[e];
    }
}

// ---------------- fp32 -> bf16 split convert (weights only) ----------------
__global__ void convert_split_kernel(const float* __restrict__ in,
                                     __nv_bfloat16* __restrict__ ohi,
                                     __nv_bfloat16* __restrict__ olo, int n4) {
    int i = blockIdx.x * blockDim.x + threadIdx.x;
    if (i < n4) {
        float4 v = ((const float4*)in)[i];
        __nv_bfloat16 h0, l0, h1, l1, h2, l2, h3, l3;
        split_bf16(v.x, h0, l0);
        split_bf16(v.y, h1, l1);
        split_bf16(v.z, h2, l2);
        split_bf16(v.w, h3, l3);
        uint2 uh, ul;
        uh.x = pack2(h0, h1); uh.y = pack2(h2, h3);
        ul.x = pack2(l0, l1); ul.y = pack2(l2, l3);
        ((uint2*)ohi)[i] = uh;
        ((uint2*)olo)[i] = ul;
    }
}

// ---------------- aggregation: warp-per-node fp32 gather, bf16-split output ----------------
// x[v] = (1+eps[li]) * h[v] + mean_{s in N(v)} h[s]
__global__ void aggregate_kernel(const float* __restrict__ h,
                                 __nv_bfloat16* __restrict__ xhi,
                                 __nv_bfloat16* __restrict__ xlo,
                                 const float* __restrict__ eps, int li) {
    int warp = (blockIdx.x * blockDim.x + threadIdx.x) >> 5;
    if (warp >= NN) return;
    int lane = threadIdx.x & 31;
    int v = warp;
    int beg = g_rowptr[v], end = g_rowptr[v + 1];
    float4 acc = make_float4(0.f, 0.f, 0.f, 0.f);
    int e = beg;
    int col = lane * 4;
#define ACC4(q) \
    acc.x += (q).x; acc.y += (q).y; acc.z += (q).z; acc.w += (q).w
    for (; e + 8 <= end; e += 8) {
        float4 a0 = *(const float4*)(h + (size_t)g_esrc[e + 0] * 128 + col);
        float4 a1 = *(const float4*)(h + (size_t)g_esrc[e + 1] * 128 + col);
        float4 a2 = *(const float4*)(h + (size_t)g_esrc[e + 2] * 128 + col);
        float4 a3 = *(const float4*)(h + (size_t)g_esrc[e + 3] * 128 + col);
        float4 a4 = *(const float4*)(h + (size_t)g_esrc[e + 4] * 128 + col);
        float4 a5 = *(const float4*)(h + (size_t)g_esrc[e + 5] * 128 + col);
        float4 a6 = *(const float4*)(h + (size_t)g_esrc[e + 6] * 128 + col);
        float4 a7 = *(const float4*)(h + (size_t)g_esrc[e + 7] * 128 + col);
        ACC4(a0); ACC4(a1); ACC4(a2); ACC4(a3);
        ACC4(a4); ACC4(a5); ACC4(a6); ACC4(a7);
    }
    for (; e + 4 <= end; e += 4) {
        float4 a0 = *(const float4*)(h + (size_t)g_esrc[e + 0] * 128 + col);
        float4 a1 = *(const float4*)(h + (size_t)g_esrc[e + 1] * 128 + col);
        float4 a2 = *(const float4*)(h + (size_t)g_esrc[e + 2] * 128 + col);
        float4 a3 = *(const float4*)(h + (size_t)g_esrc[e + 3] * 128 + col);
        ACC4(a0); ACC4(a1); ACC4(a2); ACC4(a3);
    }
    for (; e < end; ++e) {
        float4 a = *(const float4*)(h + (size_t)g_esrc[e] * 128 + col);
        ACC4(a);
    }
#undef ACC4
    float inv = g_invdeg[v];
    float sc = 1.0f + eps[li];
    float4 hv = *(const float4*)(h + (size_t)v * 128 + col);
    float4 o;
    o.x = sc * hv.x + acc.x * inv;
    o.y = sc * hv.y + acc.y * inv;
    o.z = sc * hv.z + acc.z * inv;
    o.w = sc * hv.w + acc.w * inv;
    __nv_bfloat16 h0, l0, h1, l1, h2, l2, h3, l3;
    split_bf16(o.x, h0, l0);
    split_bf16(o.y, h1, l1);
    split_bf16(o.z, h2, l2);
    split_bf16(o.w, h3, l3);
    uint2 uh, ul;
    uh.x = pack2(h0, h1); uh.y = pack2(h2, h3);
    ul.x = pack2(l0, l1); ul.y = pack2(l2, l3);
    *(uint2*)&xhi[(size_t)v * 128 + col] = uh;
    *(uint2*)&xlo[(size_t)v * 128 + col] = ul;
}

// ---------------- tensor-core GEMM via mma.sync (bf16 split, fp32 accum) ----------------
// ASPLIT=true: A-tile computed by splitting fp32 A32 in-kernel (A hi/lo ptrs unused)
template <int N, bool RELU, bool ASPLIT>
__global__ void __launch_bounds__(256) gemm_mma(
    const float* __restrict__ A32,
    const __nv_bfloat16* __restrict__ Ahi, const __nv_bfloat16* __restrict__ Alo,
    const __nv_bfloat16* __restrict__ Bhi, const __nv_bfloat16* __restrict__ Blo,
    const float* __restrict__ bias, float* __restrict__ out, int M) {
    constexpr int LD = 136;
    constexpr int NWN = N / 32;
    constexpr int NWM = 8 / NWN;
    constexpr int MW = 128 / NWM;
    constexpr int MT = MW / 16;

    extern __shared__ __nv_bfloat16 sm[];
    __nv_bfloat16* sAhi = sm;
    __nv_bfloat16* sAlo = sAhi + 128 * LD;
    __nv_bfloat16* sBhi = sAlo + 128 * LD;
    __nv_bfloat16* sBlo = sBhi + N * LD;
    __shared__ float s_bias[128];

    int tid = threadIdx.x;
    int m0 = blockIdx.x * 128;
    if (tid < N) s_bias[tid] = bias[tid];

    // stage B
    for (int i = tid; i < N * 16; i += 256) {
        int row = i >> 4;
        int c8 = (i & 15) << 3;
        *(uint4*)&sBhi[row * LD + c8] = *(const uint4*)(Bhi + (size_t)row * 128 + c8);
        *(uint4*)&sBlo[row * LD + c8] = *(const uint4*)(Blo + (size_t)row * 128 + c8);
    }
    // stage A
    if (ASPLIT) {
        for (int i = tid; i < 2048; i += 256) {
            int row = i >> 4;
            int c8 = (i & 15) << 3;
            int gm = m0 + row;
            float4 v0 = make_float4(0.f, 0.f, 0.f, 0.f);
            float4 v1 = make_float4(0.f, 0.f, 0.f, 0.f);
            if (gm < M) {
                v0 = *(const float4*)(A32 + (size_t)gm * 128 + c8);
                v1 = *(const float4*)(A32 + (size_t)gm * 128 + c8 + 4);
            }
            __nv_bfloat16 hh[8], ll[8];
            split_bf16(v0.x, hh[0], ll[0]); split_bf16(v0.y, hh[1], ll[1]);
            split_bf16(v0.z, hh[2], ll[2]); split_bf16(v0.w, hh[3], ll[3]);
            split_bf16(v1.x, hh[4], ll[4]); split_bf16(v1.y, hh[5], ll[5]);
            split_bf16(v1.z, hh[6], ll[6]); split_bf16(v1.w, hh[7], ll[7]);
            uint4 uh, ul;
            uh.x = pack2(hh[0], hh[1]); uh.y = pack2(hh[2], hh[3]);
            uh.z = pack2(hh[4], hh[5]); uh.w = pack2(hh[6], hh[7]);
            ul.x = pack2(ll[0], ll[1]); ul.y = pack2(ll[2], ll[3]);
            ul.z = pack2(ll[4], ll[5]); ul.w = pack2(ll[6], ll[7]);
            *(uint4*)&sAhi[row * LD + c8] = uh;
            *(uint4*)&sAlo[row * LD + c8] = ul;
        }
    } else {
        for (int i = tid; i < 2048; i += 256) {
            int row = i >> 4;
            int c8 = (i & 15) << 3;
            int gm = m0 + row;
            uint4 vh = make_uint4(0, 0, 0, 0), vl = make_uint4(0, 0, 0, 0);
            if (gm < M) {
                vh = *(const uint4*)(Ahi + (size_t)gm * 128 + c8);
                vl = *(const uint4*)(Alo + (size_t)gm * 128 + c8);
            }
            *(uint4*)&sAhi[row * LD + c8] = vh;
            *(uint4*)&sAlo[row * LD + c8] = vl;
        }
    }
    __syncthreads();

    int lane = tid & 31;
    int wid = tid >> 5;
    int wm = wid / NWN;
    int wn = wid % NWN;

    float acc[MT][4][4];
#pragma unroll
    for (int mt = 0; mt < MT; ++mt)
#pragma unroll
        for (int nt = 0; nt < 4; ++nt)
#pragma unroll
            for (int q = 0; q < 4; ++q) acc[mt][nt][q] = 0.f;

    const int ar = lane & 15;
    const int ak = (lane >> 4) << 3;
    const int br = (lane & 7) + ((lane >> 4) << 3);
    const int bk = ((lane >> 3) & 1) << 3;

#pragma unroll
    for (int ks = 0; ks < 8; ++ks) {
        int k0 = ks << 4;
        uint32_t ah[MT][4], al[MT][4];
#pragma unroll
        for (int mt = 0; mt < MT; ++mt) {
            int row = wm * MW + mt * 16 + ar;
            ldsm4(ah[mt], smem_u32(&sAhi[row * LD + k0 + ak]));
            ldsm4(al[mt], smem_u32(&sAlo[row * LD + k0 + ak]));
        }
        uint32_t bh[4][2], bl[4][2];
#pragma unroll
        for (int p = 0; p < 2; ++p) {
            int nrow = wn * 32 + p * 16 + br;
            uint32_t r[4];
            ldsm4(r, smem_u32(&sBhi[nrow * LD + k0 + bk]));
            bh[2 * p][0] = r[0]; bh[2 * p][1] = r[1];
            bh[2 * p + 1][0] = r[2]; bh[2 * p + 1][1] = r[3];
            ldsm4(r, smem_u32(&sBlo[nrow * LD + k0 + bk]));
            bl[2 * p][0] = r[0]; bl[2 * p][1] = r[1];
            bl[2 * p + 1][0] = r[2]; bl[2 * p + 1][1] = r[3];
        }
#pragma unroll
        for (int mt = 0; mt < MT; ++mt)
#pragma unroll
            for (int nt = 0; nt < 4; ++nt) {
                mma_bf16(acc[mt][nt], ah[mt], bh[nt]);
                mma_bf16(acc[mt][nt], ah[mt], bl[nt]);
                mma_bf16(acc[mt][nt], al[mt], bh[nt]);
            }
    }

    int r = lane >> 2;
    int c2 = (lane & 3) << 1;
#pragma unroll
    for (int mt = 0; mt < MT; ++mt) {
        int gm = m0 + wm * MW + mt * 16 + r;
#pragma unroll
        for (int nt = 0; nt < 4; ++nt) {
            int col = wn * 32 + nt * 8 + c2;
            float b0 = s_bias[col], b1 = s_bias[col + 1];
            if (gm < M) {
                float2 v = make_float2(acc[mt][nt][0] + b0, acc[mt][nt][1] + b1);
                if (RELU) { v.x = fmaxf(v.x, 0.f); v.y = fmaxf(v.y, 0.f); }
                *(float2*)(out + (size_t)gm * N + col) = v;
            }
            if (gm + 8 < M) {
                float2 v = make_float2(acc[mt][nt][2] + b0, acc[mt][nt][3] + b1);
                if (RELU) { v.x = fmaxf(v.x, 0.f); v.y = fmaxf(v.y, 0.f); }
                *(float2*)(out + (size_t)(gm + 8) * N + col) = v;
            }
        }
    }
}

// ---------------- launch ----------------
extern "C" void kernel_launch(void* const* d_in, const int* in_sizes, int n_in,
                              void* d_out, int out_size) {
    const float* inputs = (const float*)d_in[0];
    const float* fc_W   = (const float*)d_in[1];
    const float* fc_b   = (const float*)d_in[2];
    const float* W      = (const float*)d_in[3];
    const float* b      = (const float*)d_in[4];
    const float* W_last = (const float*)d_in[5];
    const float* b_last = (const float*)d_in[6];
    const float* eps    = (const float*)d_in[7];
    const int*   src    = (const int*)d_in[8];
    const int*   dst    = (const int*)d_in[9];
    float* out = (float*)d_out;

    float* hptr;
    __nv_bfloat16 *xhi, *xlo, *whi, *wlo;
    cudaGetSymbolAddress((void**)&hptr, g_h);
    cudaGetSymbolAddress((void**)&xhi, g_xhi);
    cudaGetSymbolAddress((void**)&xlo, g_xlo);
    cudaGetSymbolAddress((void**)&whi, g_whi);
    cudaGetSymbolAddress((void**)&wlo, g_wlo);

    const int SMEM128 = (2 * 128 * 136 + 2 * 128 * 136) * 2;  // 139264 B
    const int SMEM64  = (2 * 128 * 136 + 2 * 64 * 136) * 2;   // 104448 B
    cudaFuncSetAttribute(gemm_mma<128, true, true>,  cudaFuncAttributeMaxDynamicSharedMemorySize, SMEM128);
    cudaFuncSetAttribute(gemm_mma<128, true, false>, cudaFuncAttributeMaxDynamicSharedMemorySize, SMEM128);
    cudaFuncSetAttribute(gemm_mma<64, false, false>, cudaFuncAttributeMaxDynamicSharedMemorySize, SMEM64);

    // CSR build (atomic-free fill via epos)
    zero_deg_kernel<<<(NN + 255) / 256, 256>>>();
    hist_kernel<<<(NE / 4 + 255) / 256, 256>>>(dst);
    scan_kernel<<<1, 1024>>>();
    fill_kernel<<<(NE / 4 + 255) / 256, 256>>>(src, dst);

    // weight bf16 splits only (inputs split in-GEMM)
    convert_split_kernel<<<(16384 / 4 + 255) / 256, 256>>>(fc_W, whi, wlo, 16384 / 4);
    convert_split_kernel<<<(49152 / 4 + 255) / 256, 256>>>(W, whi + 16384, wlo + 16384, 49152 / 4);
    convert_split_kernel<<<(8192 / 4 + 255) / 256, 256>>>(W_last, whi + 4 * 16384, wlo + 4 * 16384, 8192 / 4);

    const int gemm_grid = (NN + 127) / 128;  // 391
    const int agg_grid  = (NN + 7) / 8;

    // input SLP: split fp32 inputs inside the GEMM
    gemm_mma<128, true, true><<<gemm_grid, 256, SMEM128>>>(
        inputs, nullptr, nullptr, whi, wlo, fc_b, hptr, NN);

    // 3 hidden GIN layers
    for (int i = 0; i < 3; ++i) {
        aggregate_kernel<<<agg_grid, 256>>>(hptr, xhi, xlo, eps, i);
        gemm_mma<128, true, false><<<gemm_grid, 256, SMEM128>>>(
            nullptr, xhi, xlo, whi + (size_t)(1 + i) * 16384, wlo + (size_t)(1 + i) * 16384,
            b + (size_t)i * 128, hptr, NN);
    }

    // last GIN layer (no relu) straight into d_out
    aggregate_kernel<<<agg_grid, 256>>>(hptr, xhi, xlo, eps, 3);
    gemm_mma<64, false, false><<<gemm_grid, 256, SMEM64>>>(
        nullptr, xhi, xlo, whi + (size_t)4 * 16384, wlo + (size_t)4 * 16384, b_last, out, NN);

    (void)in_sizes; (void)n_in; (void)out_size;
}

// round 7
// speedup vs baseline: 1.5130x; 1.0266x over previous
#include <cuda_runtime.h>
#include <cuda_bf16.h>
#include <cuda_fp16.h>
#include <cstdint>

#define NN 50000
#define NE 800000

// ---------------- device scratch (no allocs allowed) ----------------
__device__ __align__(16) float g_h[NN * 128];
__device__ __align__(16) __half g_h16[NN * 128];
__device__ __align__(16) __nv_bfloat16 g_xhi[NN * 128];
__device__ __align__(16) __nv_bfloat16 g_xlo[NN * 128];
__device__ __align__(16) __nv_bfloat16 g_whi[5 * 128 * 128];
__device__ __align__(16) __nv_bfloat16 g_wlo[5 * 128 * 128];
__device__ int   g_deg[NN];
__device__ float g_invdeg[NN];
__device__ int   g_rowptr[NN + 1];
__device__ int   g_epos[NE];
__device__ int   g_esrc[NE];

// ---------------- helpers ----------------
__device__ __forceinline__ uint32_t smem_u32(const void* p) {
    uint32_t a;
    asm("{ .reg .u64 t; cvta.to.shared.u64 t, %1; cvt.u32.u64 %0, t; }" : "=r"(a) : "l"(p));
    return a;
}

__device__ __forceinline__ void ldsm4(uint32_t* r, uint32_t addr) {
    asm volatile("ldmatrix.sync.aligned.m8n8.x4.shared.b16 {%0,%1,%2,%3}, [%4];"
                 : "=r"(r[0]), "=r"(r[1]), "=r"(r[2]), "=r"(r[3]) : "r"(addr));
}

__device__ __forceinline__ void mma_bf16(float* c, const uint32_t* a, const uint32_t* b) {
    asm volatile(
        "mma.sync.aligned.m16n8k16.row.col.f32.bf16.bf16.f32 "
        "{%0,%1,%2,%3}, {%4,%5,%6,%7}, {%8,%9}, {%0,%1,%2,%3};"
        : "+f"(c[0]), "+f"(c[1]), "+f"(c[2]), "+f"(c[3])
        : "r"(a[0]), "r"(a[1]), "r"(a[2]), "r"(a[3]), "r"(b[0]), "r"(b[1]));
}

__device__ __forceinline__ void split_bf16(float v, __nv_bfloat16& hi, __nv_bfloat16& lo) {
    hi = __float2bfloat16_rn(v);
    lo = __float2bfloat16_rn(v - __bfloat162float(hi));
}
__device__ __forceinline__ uint32_t pack2(__nv_bfloat16 a, __nv_bfloat16 b) {
    __nv_bfloat162 t = __halves2bfloat162(a, b);
    return *reinterpret_cast<uint32_t*>(&t);
}
__device__ __forceinline__ uint32_t pack2h(__half a, __half b) {
    __half2 t = __halves2half2(a, b);
    return *reinterpret_cast<uint32_t*>(&t);
}

// ---------------- CSR build ----------------
__global__ void zero_deg_kernel() {
    int v = blockIdx.x * blockDim.x + threadIdx.x;
    if (v < NN) g_deg[v] = 0;
}

__global__ void hist_kernel(const int* __restrict__ dst) {
    int i = blockIdx.x * blockDim.x + threadIdx.x;
    if (i * 4 + 3 < NE) {
        int4 d = ((const int4*)dst)[i];
        int4 p;
        p.x = atomicAdd(&g_deg[d.x], 1);
        p.y = atomicAdd(&g_deg[d.y], 1);
        p.z = atomicAdd(&g_deg[d.z], 1);
        p.w = atomicAdd(&g_deg[d.w], 1);
        ((int4*)g_epos)[i] = p;
    } else {
        for (int e = i * 4; e < NE; ++e) g_epos[e] = atomicAdd(&g_deg[dst[e]], 1);
    }
}

__global__ void scan_kernel() {
    __shared__ int partial[1024];
    int t = threadIdx.x;
    const int C = (NN + 1023) / 1024;
    int beg = t * C;
    int end = min(beg + C, NN);
    int s = 0;
    for (int v = beg; v < end; ++v) s += g_deg[v];
    partial[t] = s;
    __syncthreads();
    for (int off = 1; off < 1024; off <<= 1) {
        int val = (t >= off) ? partial[t - off] : 0;
        __syncthreads();
        partial[t] += val;
        __syncthreads();
    }
    int run = (t == 0) ? 0 : partial[t - 1];
    for (int v = beg; v < end; ++v) {
        int d = g_deg[v];
        g_rowptr[v] = run;
        g_invdeg[v] = 1.0f / (float)(d > 0 ? d : 1);
        run += d;
    }
    if (t == 1023) g_rowptr[NN] = run;
}

__global__ void fill_kernel(const int* __restrict__ src, const int* __restrict__ dst) {
    int i = blockIdx.x * blockDim.x + threadIdx.x;
    if (i * 4 + 3 < NE) {
        int4 s = ((const int4*)src)[i];
        int4 d = ((const int4*)dst)[i];
        int4 p = ((const int4*)g_epos)[i];
        g_esrc[g_rowptr[d.x] + p.x] = s.x;
        g_esrc[g_rowptr[d.y] + p.y] = s.y;
        g_esrc[g_rowptr[d.z] + p.z] = s.z;
        g_esrc[g_rowptr[d.w] + p.w] = s.w;
    } else {
        for (int e = i * 4; e < NE; ++e)
            g_esrc[g_rowptr[dst[e]] + g_epos[e]] = src[e];
    }
}

// ---------------- merged fp32 -> bf16 split convert for all 5 weight mats ----------------
// f4 layout: [0,4096) fc_W | [4096,16384) W | [16384,18432) W_last  (matches whi offsets)
__global__ void convert_weights_kernel(const float* __restrict__ fcW,
                                       const float* __restrict__ W,
                                       const float* __restrict__ WL,
                                       __nv_bfloat16* __restrict__ ohi,
                                       __nv_bfloat16* __restrict__ olo) {
    int i = blockIdx.x * blockDim.x + threadIdx.x;
    if (i >= 18432) return;
    const float* srcp;
    if (i < 4096) srcp = fcW + 4 * (size_t)i;
    else if (i < 16384) srcp = W + 4 * (size_t)(i - 4096);
    else srcp = WL + 4 * (size_t)(i - 16384);
    float4 v = *(const float4*)srcp;
    __nv_bfloat16 h0, l0, h1, l1, h2, l2, h3, l3;
    split_bf16(v.x, h0, l0);
    split_bf16(v.y, h1, l1);
    split_bf16(v.z, h2, l2);
    split_bf16(v.w, h3, l3);
    uint2 uh, ul;
    uh.x = pack2(h0, h1); uh.y = pack2(h2, h3);
    ul.x = pack2(l0, l1); ul.y = pack2(l2, l3);
    ((uint2*)ohi)[i] = uh;
    ((uint2*)olo)[i] = ul;
}

// ---------------- aggregation: warp-per-node, fp16 neighbor gather, fp32 self ----------------
// x[v] = (1+eps[li]) * h[v] + mean_{s in N(v)} h16[s]
__global__ void aggregate_kernel(const float* __restrict__ h, const __half* __restrict__ h16,
                                 __nv_bfloat16* __restrict__ xhi,
                                 __nv_bfloat16* __restrict__ xlo,
                                 const float* __restrict__ eps, int li) {
    int warp = (blockIdx.x * blockDim.x + threadIdx.x) >> 5;
    if (warp >= NN) return;
    int lane = threadIdx.x & 31;
    int v = warp;
    int beg = g_rowptr[v], end = g_rowptr[v + 1];
    float4 acc = make_float4(0.f, 0.f, 0.f, 0.f);
    int e = beg;
    int col = lane * 4;
#define GATH(uv)                                                        \
    {                                                                   \
        __half2 p0 = *reinterpret_cast<const __half2*>(&(uv).x);        \
        __half2 p1 = *reinterpret_cast<const __half2*>(&(uv).y);        \
        float2 f0 = __half22float2(p0);                                 \
        float2 f1 = __half22float2(p1);                                 \
        acc.x += f0.x; acc.y += f0.y; acc.z += f1.x; acc.w += f1.y;     \
    }
    for (; e + 8 <= end; e += 8) {
        uint2 a0 = *(const uint2*)(h16 + (size_t)g_esrc[e + 0] * 128 + col);
        uint2 a1 = *(const uint2*)(h16 + (size_t)g_esrc[e + 1] * 128 + col);
        uint2 a2 = *(const uint2*)(h16 + (size_t)g_esrc[e + 2] * 128 + col);
        uint2 a3 = *(const uint2*)(h16 + (size_t)g_esrc[e + 3] * 128 + col);
        uint2 a4 = *(const uint2*)(h16 + (size_t)g_esrc[e + 4] * 128 + col);
        uint2 a5 = *(const uint2*)(h16 + (size_t)g_esrc[e + 5] * 128 + col);
        uint2 a6 = *(const uint2*)(h16 + (size_t)g_esrc[e + 6] * 128 + col);
        uint2 a7 = *(const uint2*)(h16 + (size_t)g_esrc[e + 7] * 128 + col);
        GATH(a0); GATH(a1); GATH(a2); GATH(a3);
        GATH(a4); GATH(a5); GATH(a6); GATH(a7);
    }
    for (; e + 4 <= end; e += 4) {
        uint2 a0 = *(const uint2*)(h16 + (size_t)g_esrc[e + 0] * 128 + col);
        uint2 a1 = *(const uint2*)(h16 + (size_t)g_esrc[e + 1] * 128 + col);
        uint2 a2 = *(const uint2*)(h16 + (size_t)g_esrc[e + 2] * 128 + col);
        uint2 a3 = *(const uint2*)(h16 + (size_t)g_esrc[e + 3] * 128 + col);
        GATH(a0); GATH(a1); GATH(a2); GATH(a3);
    }
    for (; e < end; ++e) {
        uint2 a = *(const uint2*)(h16 + (size_t)g_esrc[e] * 128 + col);
        GATH(a);
    }
#undef GATH
    float inv = g_invdeg[v];
    float sc = 1.0f + eps[li];
    float4 hv = *(const float4*)(h + (size_t)v * 128 + col);
    float4 o;
    o.x = sc * hv.x + acc.x * inv;
    o.y = sc * hv.y + acc.y * inv;
    o.z = sc * hv.z + acc.z * inv;
    o.w = sc * hv.w + acc.w * inv;
    __nv_bfloat16 h0, l0, h1, l1, h2, l2, h3, l3;
    split_bf16(o.x, h0, l0);
    split_bf16(o.y, h1, l1);
    split_bf16(o.z, h2, l2);
    split_bf16(o.w, h3, l3);
    uint2 uh, ul;
    uh.x = pack2(h0, h1); uh.y = pack2(h2, h3);
    ul.x = pack2(l0, l1); ul.y = pack2(l2, l3);
    *(uint2*)&xhi[(size_t)v * 128 + col] = uh;
    *(uint2*)&xlo[(size_t)v * 128 + col] = ul;
}

// ---------------- tensor-core GEMM via mma.sync (bf16 split, fp32 accum) ----------------
// ASPLIT: A-tile from fp32 A32 split in-kernel.  H16OUT: also write fp16 shadow of out.
template <int N, bool RELU, bool ASPLIT, bool H16OUT>
__global__ void __launch_bounds__(256) gemm_mma(
    const float* __restrict__ A32,
    const __nv_bfloat16* __restrict__ Ahi, const __nv_bfloat16* __restrict__ Alo,
    const __nv_bfloat16* __restrict__ Bhi, const __nv_bfloat16* __restrict__ Blo,
    const float* __restrict__ bias, float* __restrict__ out, __half* __restrict__ out16,
    int M) {
    constexpr int LD = 136;
    constexpr int NWN = N / 32;
    constexpr int NWM = 8 / NWN;
    constexpr int MW = 128 / NWM;
    constexpr int MT = MW / 16;

    extern __shared__ __nv_bfloat16 sm[];
    __nv_bfloat16* sAhi = sm;
    __nv_bfloat16* sAlo = sAhi + 128 * LD;
    __nv_bfloat16* sBhi = sAlo + 128 * LD;
    __nv_bfloat16* sBlo = sBhi + N * LD;
    __shared__ float s_bias[128];

    int tid = threadIdx.x;
    int m0 = blockIdx.x * 128;
    if (tid < N) s_bias[tid] = bias[tid];

    // stage B
    for (int i = tid; i < N * 16; i += 256) {
        int row = i >> 4;
        int c8 = (i & 15) << 3;
        *(uint4*)&sBhi[row * LD + c8] = *(const uint4*)(Bhi + (size_t)row * 128 + c8);
        *(uint4*)&sBlo[row * LD + c8] = *(const uint4*)(Blo + (size_t)row * 128 + c8);
    }
    // stage A
    if (ASPLIT) {
        for (int i = tid; i < 2048; i += 256) {
            int row = i >> 4;
            int c8 = (i & 15) << 3;
            int gm = m0 + row;
            float4 v0 = make_float4(0.f, 0.f, 0.f, 0.f);
            float4 v1 = make_float4(0.f, 0.f, 0.f, 0.f);
            if (gm < M) {
                v0 = *(const float4*)(A32 + (size_t)gm * 128 + c8);
                v1 = *(const float4*)(A32 + (size_t)gm * 128 + c8 + 4);
            }
            __nv_bfloat16 hh[8], ll[8];
            split_bf16(v0.x, hh[0], ll[0]); split_bf16(v0.y, hh[1], ll[1]);
            split_bf16(v0.z, hh[2], ll[2]); split_bf16(v0.w, hh[3], ll[3]);
            split_bf16(v1.x, hh[4], ll[4]); split_bf16(v1.y, hh[5], ll[5]);
            split_bf16(v1.z, hh[6], ll[6]); split_bf16(v1.w, hh[7], ll[7]);
            uint4 uh, ul;
            uh.x = pack2(hh[0], hh[1]); uh.y = pack2(hh[2], hh[3]);
            uh.z = pack2(hh[4], hh[5]); uh.w = pack2(hh[6], hh[7]);
            ul.x = pack2(ll[0], ll[1]); ul.y = pack2(ll[2], ll[3]);
            ul.z = pack2(ll[4], ll[5]); ul.w = pack2(ll[6], ll[7]);
            *(uint4*)&sAhi[row * LD + c8] = uh;
            *(uint4*)&sAlo[row * LD + c8] = ul;
        }
    } else {
        for (int i = tid; i < 2048; i += 256) {
            int row = i >> 4;
            int c8 = (i & 15) << 3;
            int gm = m0 + row;
            uint4 vh = make_uint4(0, 0, 0, 0), vl = make_uint4(0, 0, 0, 0);
            if (gm < M) {
                vh = *(const uint4*)(Ahi + (size_t)gm * 128 + c8);
                vl = *(const uint4*)(Alo + (size_t)gm * 128 + c8);
            }
            *(uint4*)&sAhi[row * LD + c8] = vh;
            *(uint4*)&sAlo[row * LD + c8] = vl;
        }
    }
    __syncthreads();

    int lane = tid & 31;
    int wid = tid >> 5;
    int wm = wid / NWN;
    int wn = wid % NWN;

    float acc[MT][4][4];
#pragma unroll
    for (int mt = 0; mt < MT; ++mt)
#pragma unroll
        for (int nt = 0; nt < 4; ++nt)
#pragma unroll
            for (int q = 0; q < 4; ++q) acc[mt][nt][q] = 0.f;

    const int ar = lane & 15;
    const int ak = (lane >> 4) << 3;
    const int br = (lane & 7) + ((lane >> 4) << 3);
    const int bk = ((lane >> 3) & 1) << 3;

#pragma unroll
    for (int ks = 0; ks < 8; ++ks) {
        int k0 = ks << 4;
        uint32_t ah[MT][4], al[MT][4];
#pragma unroll
        for (int mt = 0; mt < MT; ++mt) {
            int row = wm * MW + mt * 16 + ar;
            ldsm4(ah[mt], smem_u32(&sAhi[row * LD + k0 + ak]));
            ldsm4(al[mt], smem_u32(&sAlo[row * LD + k0 + ak]));
        }
        uint32_t bh[4][2], bl[4][2];
#pragma unroll
        for (int p = 0; p < 2; ++p) {
            int nrow = wn * 32 + p * 16 + br;
            uint32_t r[4];
            ldsm4(r, smem_u32(&sBhi[nrow * LD + k0 + bk]));
            bh[2 * p][0] = r[0]; bh[2 * p][1] = r[1];
            bh[2 * p + 1][0] = r[2]; bh[2 * p + 1][1] = r[3];
            ldsm4(r, smem_u32(&sBlo[nrow * LD + k0 + bk]));
            bl[2 * p][0] = r[0]; bl[2 * p][1] = r[1];
            bl[2 * p + 1][0] = r[2]; bl[2 * p + 1][1] = r[3];
        }
#pragma unroll
        for (int mt = 0; mt < MT; ++mt)
#pragma unroll
            for (int nt = 0; nt < 4; ++nt) {
                mma_bf16(acc[mt][nt], ah[mt], bh[nt]);
                mma_bf16(acc[mt][nt], ah[mt], bl[nt]);
                mma_bf16(acc[mt][nt], al[mt], bh[nt]);
            }
    }

    int r = lane >> 2;
    int c2 = (lane & 3) << 1;
#pragma unroll
    for (int mt = 0; mt < MT; ++mt) {
        int gm = m0 + wm * MW + mt * 16 + r;
#pragma unroll
        for (int nt = 0; nt < 4; ++nt) {
            int col = wn * 32 + nt * 8 + c2;
            float b0 = s_bias[col], b1 = s_bias[col + 1];
            if (gm < M) {
                float2 v = make_float2(acc[mt][nt][0] + b0, acc[mt][nt][1] + b1);
                if (RELU) { v.x = fmaxf(v.x, 0.f); v.y = fmaxf(v.y, 0.f); }
                *(float2*)(out + (size_t)gm * N + col) = v;
                if (H16OUT)
                    *(uint32_t*)(out16 + (size_t)gm * N + col) =
                        pack2h(__float2half_rn(v.x), __float2half_rn(v.y));
            }
            if (gm + 8 < M) {
                float2 v = make_float2(acc[mt][nt][2] + b0, acc[mt][nt][3] + b1);
                if (RELU) { v.x = fmaxf(v.x, 0.f); v.y = fmaxf(v.y, 0.f); }
                *(float2*)(out + (size_t)(gm + 8) * N + col) = v;
                if (H16OUT)
                    *(uint32_t*)(out16 + (size_t)(gm + 8) * N + col) =
                        pack2h(__float2half_rn(v.x), __float2half_rn(v.y));
            }
        }
    }
}

// ---------------- launch ----------------
extern "C" void kernel_launch(void* const* d_in, const int* in_sizes, int n_in,
                              void* d_out, int out_size) {
    const float* inputs = (const float*)d_in[0];
    const float* fc_W   = (const float*)d_in[1];
    const float* fc_b   = (const float*)d_in[2];
    const float* W      = (const float*)d_in[3];
    const float* b      = (const float*)d_in[4];
    const float* W_last = (const float*)d_in[5];
    const float* b_last = (const float*)d_in[6];
    const float* eps    = (const float*)d_in[7];
    const int*   src    = (const int*)d_in[8];
    const int*   dst    = (const int*)d_in[9];
    float* out = (float*)d_out;

    float* hptr;
    __half* h16;
    __nv_bfloat16 *xhi, *xlo, *whi, *wlo;
    cudaGetSymbolAddress((void**)&hptr, g_h);
    cudaGetSymbolAddress((void**)&h16, g_h16);
    cudaGetSymbolAddress((void**)&xhi, g_xhi);
    cudaGetSymbolAddress((void**)&xlo, g_xlo);
    cudaGetSymbolAddress((void**)&whi, g_whi);
    cudaGetSymbolAddress((void**)&wlo, g_wlo);

    const int SMEM128 = (2 * 128 * 136 + 2 * 128 * 136) * 2;  // 139264 B
    const int SMEM64  = (2 * 128 * 136 + 2 * 64 * 136) * 2;   // 104448 B
    cudaFuncSetAttribute(gemm_mma<128, true, true, true>,   cudaFuncAttributeMaxDynamicSharedMemorySize, SMEM128);
    cudaFuncSetAttribute(gemm_mma<128, true, false, true>,  cudaFuncAttributeMaxDynamicSharedMemorySize, SMEM128);
    cudaFuncSetAttribute(gemm_mma<64, false, false, false>, cudaFuncAttributeMaxDynamicSharedMemorySize, SMEM64);

    // CSR build (atomic-free fill via epos)
    zero_deg_kernel<<<(NN + 255) / 256, 256>>>();
    hist_kernel<<<(NE / 4 + 255) / 256, 256>>>(dst);
    scan_kernel<<<1, 1024>>>();
    fill_kernel<<<(NE / 4 + 255) / 256, 256>>>(src, dst);

    // all weight splits in one launch
    convert_weights_kernel<<<(18432 + 255) / 256, 256>>>(fc_W, W, W_last, whi, wlo);

    const int gemm_grid = (NN + 127) / 128;  // 391
    const int agg_grid  = (NN + 7) / 8;

    // input SLP: split fp32 inputs inside the GEMM; writes h fp32 + fp16 shadow
    gemm_mma<128, true, true, true><<<gemm_grid, 256, SMEM128>>>(
        inputs, nullptr, nullptr, whi, wlo, fc_b, hptr, h16, NN);

    // 3 hidden GIN layers (gather from fp16 shadow)
    for (int i = 0; i < 3; ++i) {
        aggregate_kernel<<<agg_grid, 256>>>(hptr, h16, xhi, xlo, eps, i);
        gemm_mma<128, true, false, true><<<gemm_grid, 256, SMEM128>>>(
            nullptr, xhi, xlo, whi + (size_t)(1 + i) * 16384, wlo + (size_t)(1 + i) * 16384,
            b + (size_t)i * 128, hptr, h16, NN);
    }

    // last GIN layer (no relu) straight into d_out
    aggregate_kernel<<<agg_grid, 256>>>(hptr, h16, xhi, xlo, eps, 3);
    gemm_mma<64, false, false, false><<<gemm_grid, 256, SMEM64>>>(
        nullptr, xhi, xlo, whi + (size_t)4 * 16384, wlo + (size_t)4 * 16384, b_last, out,
        nullptr, NN);

    (void)in_sizes; (void)n_in; (void)out_size;
}